// round 3
// baseline (speedup 1.0000x reference)
#include <cuda_runtime.h>
#include <math.h>

#define B_  2
#define C_  64
#define N_  4096
#define EPSV 1e-5f

typedef unsigned long long ull;

// ---------------- scratch (no allocation allowed) ----------------
__device__ float g_q [B_ * N_ * C_];   // [b][n][c]
__device__ float g_k [B_ * N_ * C_];   // [b][n][c]
__device__ float g_v [B_ * N_ * C_];   // [b][n][c]
__device__ float g_hh[B_ * N_ * C_];   // attention out, [b][n][c]
__device__ float g_y [B_ * C_ * N_];   // residual+proj, [b][c][n]

// ---------------- packed f32x2 helpers (sm_10x) ----------------
__device__ __forceinline__ ull pack2f(float lo, float hi) {
    ull r; asm("mov.b64 %0, {%1,%2};" : "=l"(r) : "f"(lo), "f"(hi)); return r;
}
__device__ __forceinline__ float2 unpack2f(ull v) {
    float2 r; asm("mov.b64 {%0,%1}, %2;" : "=f"(r.x), "=f"(r.y) : "l"(v)); return r;
}
__device__ __forceinline__ ull fma2(ull a, ull b, ull c) {
    ull d; asm("fma.rn.f32x2 %0, %1, %2, %3;" : "=l"(d) : "l"(a), "l"(b), "l"(c)); return d;
}
__device__ __forceinline__ ull mul2(ull a, ull b) {
    ull d; asm("mul.rn.f32x2 %0, %1, %2;" : "=l"(d) : "l"(a), "l"(b)); return d;
}

// ---------------- cp.async helpers ----------------
__device__ __forceinline__ void cp_async16(unsigned s, const void* g) {
    asm volatile("cp.async.cg.shared.global [%0], [%1], 16;\n" :: "r"(s), "l"(g));
}
#define CP_COMMIT()  asm volatile("cp.async.commit_group;\n" ::: "memory")
#define CP_WAIT_1()  asm volatile("cp.async.wait_group 1;\n" ::: "memory")
#define CP_WAIT_0()  asm volatile("cp.async.wait_group 0;\n" ::: "memory")

// =================================================================
// Kernel A: q/k/v = W @ x + b   (x: [b][c][n], out: [b][n][c])
// grid (64, 2), 256 threads
// =================================================================
__global__ __launch_bounds__(256) void qkv_kernel(
    const float* __restrict__ x,
    const float* __restrict__ Wq, const float* __restrict__ bq,
    const float* __restrict__ Wk, const float* __restrict__ bk,
    const float* __restrict__ Wv, const float* __restrict__ bv)
{
    const int b  = blockIdx.y;
    const int n0 = blockIdx.x * 64;
    const int tid = threadIdx.x;

    __shared__ float xs[64][64];       // [c][n]
    __shared__ float Ws[3][64][65];    // padded weights [m][o][c]

    for (int i = tid; i < 64 * 16; i += 256) {
        int c = i >> 4, n4 = i & 15;
        float4 t = *(const float4*)(x + ((size_t)(b * C_ + c)) * N_ + n0 + n4 * 4);
        xs[c][n4*4+0] = t.x; xs[c][n4*4+1] = t.y; xs[c][n4*4+2] = t.z; xs[c][n4*4+3] = t.w;
    }
    for (int i = tid; i < 64 * 16; i += 256) {
        int o = i >> 4, c4 = i & 15;
        float4 tq = *(const float4*)(Wq + o * 64 + c4 * 4);
        float4 tk = *(const float4*)(Wk + o * 64 + c4 * 4);
        float4 tv = *(const float4*)(Wv + o * 64 + c4 * 4);
        Ws[0][o][c4*4+0]=tq.x; Ws[0][o][c4*4+1]=tq.y; Ws[0][o][c4*4+2]=tq.z; Ws[0][o][c4*4+3]=tq.w;
        Ws[1][o][c4*4+0]=tk.x; Ws[1][o][c4*4+1]=tk.y; Ws[1][o][c4*4+2]=tk.z; Ws[1][o][c4*4+3]=tk.w;
        Ws[2][o][c4*4+0]=tv.x; Ws[2][o][c4*4+1]=tv.y; Ws[2][o][c4*4+2]=tv.z; Ws[2][o][c4*4+3]=tv.w;
    }
    __syncthreads();

    const int nb = tid & 15;
    const int ob = tid >> 4;

    float acc[3][4][4];
    #pragma unroll
    for (int m = 0; m < 3; m++)
        #pragma unroll
        for (int i = 0; i < 4; i++)
            #pragma unroll
            for (int j = 0; j < 4; j++) acc[m][i][j] = 0.f;

    #pragma unroll 4
    for (int c = 0; c < 64; c++) {
        float xv[4];
        #pragma unroll
        for (int ni = 0; ni < 4; ni++) xv[ni] = xs[c][nb + 16 * ni];
        #pragma unroll
        for (int m = 0; m < 3; m++) {
            float wv[4];
            #pragma unroll
            for (int oi = 0; oi < 4; oi++) wv[oi] = Ws[m][ob * 4 + oi][c];
            #pragma unroll
            for (int oi = 0; oi < 4; oi++)
                #pragma unroll
                for (int ni = 0; ni < 4; ni++)
                    acc[m][oi][ni] = fmaf(wv[oi], xv[ni], acc[m][oi][ni]);
        }
    }

    float* outs[3] = { g_q, g_k, g_v };
    const float* biases[3] = { bq, bk, bv };
    #pragma unroll
    for (int m = 0; m < 3; m++) {
        float* dst = outs[m];
        #pragma unroll
        for (int oi = 0; oi < 4; oi++) {
            int o = ob * 4 + oi;
            float bias = biases[m][o];
            #pragma unroll
            for (int ni = 0; ni < 4; ni++) {
                int n = n0 + nb + 16 * ni;
                dst[((size_t)b * N_ + n) * C_ + o] = acc[m][oi][ni] + bias;
            }
        }
    }
}

// =================================================================
// Kernel B: flash attention v2.
// grid (64, 2), 256 threads (8 warps -> 2/SMSP).
// Each query owned by 4 lanes, 16 channels each, packed f32x2 math.
// Double-buffered cp.async K/V tiles of 32 keys.
// =================================================================
#define KT 32   // keys per tile

__global__ __launch_bounds__(256) void attn_kernel()
{
    const int b   = blockIdx.y;
    const int q0  = blockIdx.x * 64;
    const int tid = threadIdx.x;
    const int warp = tid >> 5, lane = tid & 31;
    const int qi      = warp * 8 + (lane >> 2);   // 0..63
    const int quarter = lane & 3;                 // 16-channel group

    __shared__ float Ks[2][KT][64];
    __shared__ float Vs[2][KT][64];

    const unsigned ks_base = (unsigned)__cvta_generic_to_shared(&Ks[0][0][0]);
    const unsigned vs_base = (unsigned)__cvta_generic_to_shared(&Vs[0][0][0]);

    // q registers: 16 floats = 8 packed pairs
    ull q2[8];
    {
        const ull* qp = (const ull*)(g_q + ((size_t)b * N_ + q0 + qi) * C_ + quarter * 16);
        #pragma unroll
        for (int i = 0; i < 8; i++) q2[i] = qp[i];
    }
    ull o2[8];
    #pragma unroll
    for (int i = 0; i < 8; i++) o2[i] = 0ull;
    float mval = -1e30f, lsum = 0.f;

    const float* kbatch = g_k + (size_t)b * N_ * C_;
    const float* vbatch = g_v + (size_t)b * N_ * C_;

    // prefetch tile 0
    {
        const float4* kp = (const float4*)kbatch;
        const float4* vp = (const float4*)vbatch;
        #pragma unroll
        for (int i = 0; i < 2; i++) {
            int e = tid + 256 * i;                  // 0..511 float4s
            cp_async16(ks_base + e * 16, kp + e);
            cp_async16(vs_base + e * 16, vp + e);
        }
        CP_COMMIT();
    }

    const int ntiles = N_ / KT;   // 128
    for (int t = 0; t < ntiles; t++) {
        if (t + 1 < ntiles) {
            int buf = (t + 1) & 1;
            const float4* kp = (const float4*)(kbatch + (size_t)(t + 1) * KT * 64);
            const float4* vp = (const float4*)(vbatch + (size_t)(t + 1) * KT * 64);
            unsigned ks = ks_base + buf * (KT * 64 * 4);
            unsigned vs = vs_base + buf * (KT * 64 * 4);
            #pragma unroll
            for (int i = 0; i < 2; i++) {
                int e = tid + 256 * i;
                cp_async16(ks + e * 16, kp + e);
                cp_async16(vs + e * 16, vp + e);
            }
            CP_COMMIT();
            CP_WAIT_1();
        } else {
            CP_WAIT_0();
        }
        __syncthreads();

        const float* Kb = &Ks[t & 1][0][quarter * 16];
        const float* Vb = &Vs[t & 1][0][quarter * 16];

        #pragma unroll 4
        for (int j = 0; j < KT; j++) {
            const ulonglong2* Kr = (const ulonglong2*)(Kb + j * 64);
            const ulonglong2* Vr = (const ulonglong2*)(Vb + j * 64);
            ulonglong2 ka = Kr[0], kb2 = Kr[1], kc = Kr[2], kd = Kr[3];

            ull acc0 = mul2(q2[0], ka.x);
            ull acc1 = mul2(q2[1], ka.y);
            acc0 = fma2(q2[2], kb2.x, acc0);
            acc1 = fma2(q2[3], kb2.y, acc1);
            acc0 = fma2(q2[4], kc.x,  acc0);
            acc1 = fma2(q2[5], kc.y,  acc1);
            acc0 = fma2(q2[6], kd.x,  acc0);
            acc1 = fma2(q2[7], kd.y,  acc1);

            // issue V loads before the shfl chain so LDS latency overlaps
            ulonglong2 va = Vr[0], vb2 = Vr[1], vc = Vr[2], vd = Vr[3];

            float2 a = unpack2f(acc0);
            float2 c = unpack2f(acc1);
            float s = (a.x + a.y) + (c.x + c.y);
            s += __shfl_xor_sync(0xffffffffu, s, 1);
            s += __shfl_xor_sync(0xffffffffu, s, 2);

            if (s > mval) {              // rare (~ln N per query)
                float sc = __expf(mval - s);
                mval = s;
                lsum *= sc;
                ull scp = pack2f(sc, sc);
                #pragma unroll
                for (int i = 0; i < 8; i++) o2[i] = mul2(o2[i], scp);
            }
            float p = __expf(s - mval);
            lsum += p;
            ull pp = pack2f(p, p);

            o2[0] = fma2(pp, va.x,  o2[0]);
            o2[1] = fma2(pp, va.y,  o2[1]);
            o2[2] = fma2(pp, vb2.x, o2[2]);
            o2[3] = fma2(pp, vb2.y, o2[3]);
            o2[4] = fma2(pp, vc.x,  o2[4]);
            o2[5] = fma2(pp, vc.y,  o2[5]);
            o2[6] = fma2(pp, vd.x,  o2[6]);
            o2[7] = fma2(pp, vd.y,  o2[7]);
        }
        __syncthreads();   // all warps done reading buf[t&1] before refill
    }

    const float inv = 1.f / lsum;
    ull ip = pack2f(inv, inv);
    ull* op = (ull*)(g_hh + ((size_t)b * N_ + q0 + qi) * C_ + quarter * 16);
    #pragma unroll
    for (int i = 0; i < 8; i++) op[i] = mul2(o2[i], ip);
}

// =================================================================
// Kernel C: y = x + Wp @ hh + bp   (out layout [b][c][n])
// grid (32, 2), 256 threads, n-tile of 128
// =================================================================
__global__ __launch_bounds__(256) void proj_kernel(
    const float* __restrict__ x,
    const float* __restrict__ Wp, const float* __restrict__ bp)
{
    const int b  = blockIdx.y;
    const int n0 = blockIdx.x * 128;
    const int tid = threadIdx.x;

    __shared__ float hs[128][65];
    __shared__ float Wps[64][65];

    for (int i = tid; i < 128 * 16; i += 256) {
        int n = i >> 4, c4 = i & 15;
        float4 t = *(const float4*)(g_hh + ((size_t)b * N_ + n0 + n) * C_ + c4 * 4);
        hs[n][c4*4+0] = t.x; hs[n][c4*4+1] = t.y; hs[n][c4*4+2] = t.z; hs[n][c4*4+3] = t.w;
    }
    for (int i = tid; i < 64 * 16; i += 256) {
        int o = i >> 4, c4 = i & 15;
        float4 t = *(const float4*)(Wp + o * 64 + c4 * 4);
        Wps[o][c4*4+0] = t.x; Wps[o][c4*4+1] = t.y; Wps[o][c4*4+2] = t.z; Wps[o][c4*4+3] = t.w;
    }
    __syncthreads();

    const int nb = tid & 15;
    const int ob = tid >> 4;

    float acc[4][8];
    #pragma unroll
    for (int i = 0; i < 4; i++)
        #pragma unroll
        for (int j = 0; j < 8; j++) acc[i][j] = 0.f;

    #pragma unroll 4
    for (int c = 0; c < 64; c++) {
        float hv[8];
        #pragma unroll
        for (int j = 0; j < 8; j++) hv[j] = hs[nb + 16 * j][c];
        float wv[4];
        #pragma unroll
        for (int i = 0; i < 4; i++) wv[i] = Wps[ob * 4 + i][c];
        #pragma unroll
        for (int i = 0; i < 4; i++)
            #pragma unroll
            for (int j = 0; j < 8; j++)
                acc[i][j] = fmaf(wv[i], hv[j], acc[i][j]);
    }

    #pragma unroll
    for (int i = 0; i < 4; i++) {
        int o = ob * 4 + i;
        float bias = bp[o];
        #pragma unroll
        for (int j = 0; j < 8; j++) {
            int n = n0 + nb + 16 * j;
            size_t idx = ((size_t)(b * C_ + o)) * N_ + n;
            g_y[idx] = acc[i][j] + bias + x[idx];
        }
    }
}

// =================================================================
// Kernel D: GroupNorm(32) + Swish.  grid (32, 2), 256 threads.
// =================================================================
__global__ __launch_bounds__(256) void gnorm_kernel(
    const float* __restrict__ gamma, const float* __restrict__ beta,
    float* __restrict__ out)
{
    const int b = blockIdx.y, g = blockIdx.x;
    const int tid = threadIdx.x;
    const size_t base = ((size_t)(b * C_ + g * 2)) * N_;
    const float* yb = g_y + base;

    float vals[32];
    float s = 0.f, sq = 0.f;
    #pragma unroll
    for (int i = 0; i < 32; i++) {
        float v = yb[tid + 256 * i];
        vals[i] = v;
        s += v;
        sq = fmaf(v, v, sq);
    }
    #pragma unroll
    for (int off = 16; off; off >>= 1) {
        s  += __shfl_xor_sync(0xffffffffu, s,  off);
        sq += __shfl_xor_sync(0xffffffffu, sq, off);
    }
    __shared__ float red[16];
    if ((tid & 31) == 0) { red[tid >> 5] = s; red[8 + (tid >> 5)] = sq; }
    __syncthreads();
    float S  = red[0] + red[1] + red[2] + red[3] + red[4] + red[5] + red[6] + red[7];
    float SQ = red[8] + red[9] + red[10] + red[11] + red[12] + red[13] + red[14] + red[15];

    const float mean = S * (1.f / 8192.f);
    const float var  = SQ * (1.f / 8192.f) - mean * mean;
    const float rinv = rsqrtf(var + EPSV);

    const float g0 = gamma[g * 2], g1 = gamma[g * 2 + 1];
    const float b0 = beta[g * 2],  b1 = beta[g * 2 + 1];

    float* ob = out + base;
    #pragma unroll
    for (int i = 0; i < 32; i++) {
        int e = tid + 256 * i;
        float gm = (e < N_) ? g0 : g1;
        float bt = (e < N_) ? b0 : b1;
        float yn = (vals[i] - mean) * rinv * gm + bt;
        ob[e] = yn / (1.f + __expf(-yn));
    }
}

// =================================================================
extern "C" void kernel_launch(void* const* d_in, const int* in_sizes, int n_in,
                              void* d_out, int out_size)
{
    const float* x     = (const float*)d_in[0];
    const float* Wq    = (const float*)d_in[1];
    const float* bq    = (const float*)d_in[2];
    const float* Wk    = (const float*)d_in[3];
    const float* bk    = (const float*)d_in[4];
    const float* Wv    = (const float*)d_in[5];
    const float* bv    = (const float*)d_in[6];
    const float* Wp    = (const float*)d_in[7];
    const float* bp    = (const float*)d_in[8];
    const float* gamma = (const float*)d_in[9];
    const float* beta  = (const float*)d_in[10];
    float* out = (float*)d_out;

    qkv_kernel<<<dim3(64, 2), 256>>>(x, Wq, bq, Wk, bk, Wv, bv);
    attn_kernel<<<dim3(64, 2), 256>>>();
    proj_kernel<<<dim3(32, 2), 256>>>(x, Wp, bp);
    gnorm_kernel<<<dim3(32, 2), 256>>>(gamma, beta, out);
}

// round 4
// speedup vs baseline: 2.9339x; 2.9339x over previous
#include <cuda_runtime.h>
#include <math.h>

#define B_  2
#define C_  64
#define N_  4096
#define EPSV 1e-5f

#define KT      32                 // keys per tile (per range)
#define NTILES  (2048 / KT)        // 64 iterations, each range advances KT keys
#define VOFF    8192               // float offset of V region in dyn smem
#define SMEM_BYTES (16384 * 4)     // 64 KB: K 8192 floats + V 8192 floats

typedef unsigned long long ull;

// ---------------- scratch (no allocation allowed) ----------------
__device__ float g_q [B_ * N_ * C_];   // [b][n][c]
__device__ float g_k [B_ * N_ * C_];   // [b][n][c]
__device__ float g_v [B_ * N_ * C_];   // [b][n][c]
__device__ float g_hh[B_ * N_ * C_];   // attention out, [b][n][c]
__device__ float g_y [B_ * C_ * N_];   // residual+proj, [b][c][n]

// ---------------- packed f32x2 helpers (sm_10x) ----------------
__device__ __forceinline__ ull pack2f(float lo, float hi) {
    ull r; asm("mov.b64 %0, {%1,%2};" : "=l"(r) : "f"(lo), "f"(hi)); return r;
}
__device__ __forceinline__ float2 unpack2f(ull v) {
    float2 r; asm("mov.b64 {%0,%1}, %2;" : "=f"(r.x), "=f"(r.y) : "l"(v)); return r;
}
__device__ __forceinline__ ull fma2(ull a, ull b, ull c) {
    ull d; asm("fma.rn.f32x2 %0, %1, %2, %3;" : "=l"(d) : "l"(a), "l"(b), "l"(c)); return d;
}
__device__ __forceinline__ ull mul2(ull a, ull b) {
    ull d; asm("mul.rn.f32x2 %0, %1, %2;" : "=l"(d) : "l"(a), "l"(b)); return d;
}
__device__ __forceinline__ ull add2(ull a, ull b) {
    ull d; asm("add.rn.f32x2 %0, %1, %2;" : "=l"(d) : "l"(a), "l"(b)); return d;
}

// ---------------- cp.async helpers ----------------
__device__ __forceinline__ void cp_async16(unsigned s, const void* g) {
    asm volatile("cp.async.cg.shared.global [%0], [%1], 16;\n" :: "r"(s), "l"(g));
}
#define CP_COMMIT()  asm volatile("cp.async.commit_group;\n" ::: "memory")
#define CP_WAIT_1()  asm volatile("cp.async.wait_group 1;\n" ::: "memory")
#define CP_WAIT_0()  asm volatile("cp.async.wait_group 0;\n" ::: "memory")

// =================================================================
// Kernel A: q/k/v = W @ x + b   (x: [b][c][n], out: [b][n][c])
// grid (64, 2), 256 threads
// =================================================================
__global__ __launch_bounds__(256) void qkv_kernel(
    const float* __restrict__ x,
    const float* __restrict__ Wq, const float* __restrict__ bq,
    const float* __restrict__ Wk, const float* __restrict__ bk,
    const float* __restrict__ Wv, const float* __restrict__ bv)
{
    const int b  = blockIdx.y;
    const int n0 = blockIdx.x * 64;
    const int tid = threadIdx.x;

    __shared__ float xs[64][64];       // [c][n]
    __shared__ float Ws[3][64][65];    // padded weights [m][o][c]

    for (int i = tid; i < 64 * 16; i += 256) {
        int c = i >> 4, n4 = i & 15;
        float4 t = *(const float4*)(x + ((size_t)(b * C_ + c)) * N_ + n0 + n4 * 4);
        xs[c][n4*4+0] = t.x; xs[c][n4*4+1] = t.y; xs[c][n4*4+2] = t.z; xs[c][n4*4+3] = t.w;
    }
    for (int i = tid; i < 64 * 16; i += 256) {
        int o = i >> 4, c4 = i & 15;
        float4 tq = *(const float4*)(Wq + o * 64 + c4 * 4);
        float4 tk = *(const float4*)(Wk + o * 64 + c4 * 4);
        float4 tv = *(const float4*)(Wv + o * 64 + c4 * 4);
        Ws[0][o][c4*4+0]=tq.x; Ws[0][o][c4*4+1]=tq.y; Ws[0][o][c4*4+2]=tq.z; Ws[0][o][c4*4+3]=tq.w;
        Ws[1][o][c4*4+0]=tk.x; Ws[1][o][c4*4+1]=tk.y; Ws[1][o][c4*4+2]=tk.z; Ws[1][o][c4*4+3]=tk.w;
        Ws[2][o][c4*4+0]=tv.x; Ws[2][o][c4*4+1]=tv.y; Ws[2][o][c4*4+2]=tv.z; Ws[2][o][c4*4+3]=tv.w;
    }
    __syncthreads();

    const int nb = tid & 15;
    const int ob = tid >> 4;

    float acc[3][4][4];
    #pragma unroll
    for (int m = 0; m < 3; m++)
        #pragma unroll
        for (int i = 0; i < 4; i++)
            #pragma unroll
            for (int j = 0; j < 4; j++) acc[m][i][j] = 0.f;

    #pragma unroll 4
    for (int c = 0; c < 64; c++) {
        float xv[4];
        #pragma unroll
        for (int ni = 0; ni < 4; ni++) xv[ni] = xs[c][nb + 16 * ni];
        #pragma unroll
        for (int m = 0; m < 3; m++) {
            float wv[4];
            #pragma unroll
            for (int oi = 0; oi < 4; oi++) wv[oi] = Ws[m][ob * 4 + oi][c];
            #pragma unroll
            for (int oi = 0; oi < 4; oi++)
                #pragma unroll
                for (int ni = 0; ni < 4; ni++)
                    acc[m][oi][ni] = fmaf(wv[oi], xv[ni], acc[m][oi][ni]);
        }
    }

    float* outs[3] = { g_q, g_k, g_v };
    const float* biases[3] = { bq, bk, bv };
    #pragma unroll
    for (int m = 0; m < 3; m++) {
        float* dst = outs[m];
        #pragma unroll
        for (int oi = 0; oi < 4; oi++) {
            int o = ob * 4 + oi;
            float bias = biases[m][o];
            #pragma unroll
            for (int ni = 0; ni < 4; ni++) {
                int n = n0 + nb + 16 * ni;
                dst[((size_t)b * N_ + n) * C_ + o] = acc[m][oi][ni] + bias;
            }
        }
    }
}

// =================================================================
// Kernel B: flash attention v3 (key-split x2 + f32x2 + cp.async).
// grid (64, 2), 256 threads.
// Warps 0-3: keys [0,2048); warps 4-7: keys [2048,4096).
// Per warp: R1 decomposition — 16 queries, lane pair per query,
// 32 channels per lane, ONE shfl per key, broadcast LDS.
// =================================================================
__global__ __launch_bounds__(256, 1) void attn_kernel()
{
    extern __shared__ float dsm[];    // 64 KB: K [0,8192), V [8192,16384)

    const int b    = blockIdx.y;
    const int q0   = blockIdx.x * 64;
    const int tid  = threadIdx.x;
    const int warp = tid >> 5, lane = tid & 31;
    const int range = warp >> 2;                  // 0 or 1 (key half)
    const int qi    = (warp & 3) * 16 + (lane & 15);
    const int half  = lane >> 4;                  // 32-channel half

    const unsigned smem_u32 = (unsigned)__cvta_generic_to_shared(dsm);

    // q registers: 32 floats = 16 packed pairs
    ull q2[16];
    {
        const ull* qp = (const ull*)(g_q + ((size_t)b * N_ + q0 + qi) * C_ + half * 32);
        #pragma unroll
        for (int i = 0; i < 16; i++) q2[i] = qp[i];
    }
    ull o2[16];
    #pragma unroll
    for (int i = 0; i < 16; i++) o2[i] = 0ull;
    float mval = -1e30f, lsum = 0.f;

    const float* kbatch = g_k + (size_t)b * N_ * C_;
    const float* vbatch = g_v + (size_t)b * N_ * C_;

    // tile loader: 4 sub-tiles (K r0, K r1, V r0, V r1), 512 float4 each
    auto load_tiles = [&](int t, int buf) {
        #pragma unroll
        for (int i = 0; i < 8; i++) {
            int e    = tid + 256 * i;      // 0..2047
            int tile = e >> 9;             // 0:Kr0 1:Kr1 2:Vr0 3:Vr1
            int elem = e & 511;            // float4 within tile
            int r    = tile & 1;
            int isv  = tile >> 1;
            const float* gbase = (isv ? vbatch : kbatch) +
                                 ((size_t)(r * 2048 + t * KT)) * 64;
            unsigned dst = (isv ? VOFF : 0) + (unsigned)(r * 2 + buf) * (KT * 64) + elem * 4;
            cp_async16(smem_u32 + dst * 4, (const float4*)gbase + elem);
        }
        CP_COMMIT();
    };

    load_tiles(0, 0);

    for (int t = 0; t < NTILES; t++) {
        if (t + 1 < NTILES) { load_tiles(t + 1, (t + 1) & 1); CP_WAIT_1(); }
        else                { CP_WAIT_0(); }
        __syncthreads();

        const float* Kb = dsm + (range * 2 + (t & 1)) * (KT * 64) + half * 32;
        const float* Vb = Kb + VOFF;

        #pragma unroll 4
        for (int j = 0; j < KT; j++) {
            // K row: 32 floats = 8 LDS.128, pure broadcast within each half
            ull kv[16];
            {
                const ulonglong2* Kr = (const ulonglong2*)(Kb + j * 64);
                #pragma unroll
                for (int i2 = 0; i2 < 8; i2++) {
                    ulonglong2 tt = Kr[i2];
                    kv[2*i2] = tt.x; kv[2*i2+1] = tt.y;
                }
            }
            ull a0 = mul2(q2[0], kv[0]);
            ull a1 = mul2(q2[1], kv[1]);
            ull a2 = mul2(q2[2], kv[2]);
            ull a3 = mul2(q2[3], kv[3]);
            #pragma unroll
            for (int i2 = 1; i2 < 4; i2++) {
                a0 = fma2(q2[4*i2+0], kv[4*i2+0], a0);
                a1 = fma2(q2[4*i2+1], kv[4*i2+1], a1);
                a2 = fma2(q2[4*i2+2], kv[4*i2+2], a2);
                a3 = fma2(q2[4*i2+3], kv[4*i2+3], a3);
            }
            float2 sp = unpack2f(add2(add2(a0, a1), add2(a2, a3)));
            float s = sp.x + sp.y;
            s += __shfl_xor_sync(0xffffffffu, s, 16);   // one shfl per key

            if (s > mval) {                 // rare (~ln N per query)
                float sc = __expf(mval - s);
                mval = s;
                lsum *= sc;
                ull scp = pack2f(sc, sc);
                #pragma unroll
                for (int i = 0; i < 16; i++) o2[i] = mul2(o2[i], scp);
            }
            float p = __expf(s - mval);
            lsum += p;
            ull pp = pack2f(p, p);

            {
                const ulonglong2* Vr = (const ulonglong2*)(Vb + j * 64);
                #pragma unroll
                for (int i2 = 0; i2 < 8; i2++) {
                    ulonglong2 tt = Vr[i2];
                    o2[2*i2]   = fma2(pp, tt.x, o2[2*i2]);
                    o2[2*i2+1] = fma2(pp, tt.y, o2[2*i2+1]);
                }
            }
        }
        __syncthreads();   // all warps done with buf (t&1) before refill
    }

    // -------- merge range B partials into range A, normalize, store ------
    // overlay staging arrays on the (now dead) K region of dyn smem
    float* So = dsm;                 // [64][68] padded
    float* Sm = dsm + 64 * 68;       // [64]
    float* Sl = Sm + 64;             // [64]

    if (range == 1) {
        ull* d2 = (ull*)(So + qi * 68 + half * 32);
        #pragma unroll
        for (int i = 0; i < 16; i++) d2[i] = o2[i];
        Sm[qi] = mval; Sl[qi] = lsum;     // redundant across halves: same value
    }
    __syncthreads();
    if (range == 0) {
        float mB = Sm[qi], lB = Sl[qi];
        float mx = fmaxf(mval, mB);
        float fa = __expf(mval - mx), fb = __expf(mB - mx);
        float l  = fmaf(lsum, fa, lB * fb);
        float ca = fa / l, cb = fb / l;
        ull cap = pack2f(ca, ca), cbp = pack2f(cb, cb);
        const ull* s2 = (const ull*)(So + qi * 68 + half * 32);
        ull* op = (ull*)(g_hh + ((size_t)b * N_ + q0 + qi) * C_ + half * 32);
        #pragma unroll
        for (int i = 0; i < 16; i++) {
            ull t = mul2(o2[i], cap);
            op[i] = fma2(cbp, s2[i], t);
        }
    }
}

// =================================================================
// Kernel C: y = x + Wp @ hh + bp   (out layout [b][c][n])
// grid (32, 2), 256 threads, n-tile of 128
// =================================================================
__global__ __launch_bounds__(256) void proj_kernel(
    const float* __restrict__ x,
    const float* __restrict__ Wp, const float* __restrict__ bp)
{
    const int b  = blockIdx.y;
    const int n0 = blockIdx.x * 128;
    const int tid = threadIdx.x;

    __shared__ float hs[128][65];
    __shared__ float Wps[64][65];

    for (int i = tid; i < 128 * 16; i += 256) {
        int n = i >> 4, c4 = i & 15;
        float4 t = *(const float4*)(g_hh + ((size_t)b * N_ + n0 + n) * C_ + c4 * 4);
        hs[n][c4*4+0] = t.x; hs[n][c4*4+1] = t.y; hs[n][c4*4+2] = t.z; hs[n][c4*4+3] = t.w;
    }
    for (int i = tid; i < 64 * 16; i += 256) {
        int o = i >> 4, c4 = i & 15;
        float4 t = *(const float4*)(Wp + o * 64 + c4 * 4);
        Wps[o][c4*4+0] = t.x; Wps[o][c4*4+1] = t.y; Wps[o][c4*4+2] = t.z; Wps[o][c4*4+3] = t.w;
    }
    __syncthreads();

    const int nb = tid & 15;
    const int ob = tid >> 4;

    float acc[4][8];
    #pragma unroll
    for (int i = 0; i < 4; i++)
        #pragma unroll
        for (int j = 0; j < 8; j++) acc[i][j] = 0.f;

    #pragma unroll 4
    for (int c = 0; c < 64; c++) {
        float hv[8];
        #pragma unroll
        for (int j = 0; j < 8; j++) hv[j] = hs[nb + 16 * j][c];
        float wv[4];
        #pragma unroll
        for (int i = 0; i < 4; i++) wv[i] = Wps[ob * 4 + i][c];
        #pragma unroll
        for (int i = 0; i < 4; i++)
            #pragma unroll
            for (int j = 0; j < 8; j++)
                acc[i][j] = fmaf(wv[i], hv[j], acc[i][j]);
    }

    #pragma unroll
    for (int i = 0; i < 4; i++) {
        int o = ob * 4 + i;
        float bias = bp[o];
        #pragma unroll
        for (int j = 0; j < 8; j++) {
            int n = n0 + nb + 16 * j;
            size_t idx = ((size_t)(b * C_ + o)) * N_ + n;
            g_y[idx] = acc[i][j] + bias + x[idx];
        }
    }
}

// =================================================================
// Kernel D: GroupNorm(32) + Swish.  grid (32, 2), 256 threads.
// =================================================================
__global__ __launch_bounds__(256) void gnorm_kernel(
    const float* __restrict__ gamma, const float* __restrict__ beta,
    float* __restrict__ out)
{
    const int b = blockIdx.y, g = blockIdx.x;
    const int tid = threadIdx.x;
    const size_t base = ((size_t)(b * C_ + g * 2)) * N_;
    const float* yb = g_y + base;

    float vals[32];
    float s = 0.f, sq = 0.f;
    #pragma unroll
    for (int i = 0; i < 32; i++) {
        float v = yb[tid + 256 * i];
        vals[i] = v;
        s += v;
        sq = fmaf(v, v, sq);
    }
    #pragma unroll
    for (int off = 16; off; off >>= 1) {
        s  += __shfl_xor_sync(0xffffffffu, s,  off);
        sq += __shfl_xor_sync(0xffffffffu, sq, off);
    }
    __shared__ float red[16];
    if ((tid & 31) == 0) { red[tid >> 5] = s; red[8 + (tid >> 5)] = sq; }
    __syncthreads();
    float S  = red[0] + red[1] + red[2] + red[3] + red[4] + red[5] + red[6] + red[7];
    float SQ = red[8] + red[9] + red[10] + red[11] + red[12] + red[13] + red[14] + red[15];

    const float mean = S * (1.f / 8192.f);
    const float var  = SQ * (1.f / 8192.f) - mean * mean;
    const float rinv = rsqrtf(var + EPSV);

    const float g0 = gamma[g * 2], g1 = gamma[g * 2 + 1];
    const float b0 = beta[g * 2],  b1 = beta[g * 2 + 1];

    float* ob = out + base;
    #pragma unroll
    for (int i = 0; i < 32; i++) {
        int e = tid + 256 * i;
        float gm = (e < N_) ? g0 : g1;
        float bt = (e < N_) ? b0 : b1;
        float yn = (vals[i] - mean) * rinv * gm + bt;
        ob[e] = yn / (1.f + __expf(-yn));
    }
}

// =================================================================
extern "C" void kernel_launch(void* const* d_in, const int* in_sizes, int n_in,
                              void* d_out, int out_size)
{
    const float* x     = (const float*)d_in[0];
    const float* Wq    = (const float*)d_in[1];
    const float* bq    = (const float*)d_in[2];
    const float* Wk    = (const float*)d_in[3];
    const float* bk    = (const float*)d_in[4];
    const float* Wv    = (const float*)d_in[5];
    const float* bv    = (const float*)d_in[6];
    const float* Wp    = (const float*)d_in[7];
    const float* bp    = (const float*)d_in[8];
    const float* gamma = (const float*)d_in[9];
    const float* beta  = (const float*)d_in[10];
    float* out = (float*)d_out;

    cudaFuncSetAttribute(attn_kernel,
                         cudaFuncAttributeMaxDynamicSharedMemorySize, SMEM_BYTES);

    qkv_kernel<<<dim3(64, 2), 256>>>(x, Wq, bq, Wk, bk, Wv, bv);
    attn_kernel<<<dim3(64, 2), 256, SMEM_BYTES>>>();
    proj_kernel<<<dim3(32, 2), 256>>>(x, Wp, bp);
    gnorm_kernel<<<dim3(32, 2), 256>>>(gamma, beta, out);
}

// round 10
// speedup vs baseline: 3.2626x; 1.1120x over previous
#include <cuda_runtime.h>
#include <math.h>

#define B_  2
#define C_  64
#define N_  4096
#define EPSV 1e-5f

#define NRANGE  4                  // key ranges (warps 0-3, 4-7, 8-11, 12-15)
#define KEYS_PER_RANGE 1024
#define KT      16                 // keys per tile per range
#define NTILES  (KEYS_PER_RANGE / KT)   // 64
#define VOFF    8192               // float offset of V region in dyn smem
#define SMEM_BYTES (16384 * 4)     // 64 KB

typedef unsigned long long ull;

// ---------------- scratch (no allocation allowed) ----------------
__device__ float g_q [B_ * N_ * C_];   // [b][n][c]
__device__ float g_k [B_ * N_ * C_];   // [b][n][c]
__device__ float g_v [B_ * N_ * C_];   // [b][n][c]
__device__ float g_hh[B_ * N_ * C_];   // attention out, [b][n][c]
__device__ float g_y [B_ * C_ * N_];   // residual+proj, [b][c][n]

// ---------------- packed f32x2 helpers (sm_10x) ----------------
__device__ __forceinline__ ull pack2f(float lo, float hi) {
    ull r; asm("mov.b64 %0, {%1,%2};" : "=l"(r) : "f"(lo), "f"(hi)); return r;
}
__device__ __forceinline__ float2 unpack2f(ull v) {
    float2 r; asm("mov.b64 {%0,%1}, %2;" : "=f"(r.x), "=f"(r.y) : "l"(v)); return r;
}
__device__ __forceinline__ ull fma2(ull a, ull b, ull c) {
    ull d; asm("fma.rn.f32x2 %0, %1, %2, %3;" : "=l"(d) : "l"(a), "l"(b), "l"(c)); return d;
}
__device__ __forceinline__ ull mul2(ull a, ull b) {
    ull d; asm("mul.rn.f32x2 %0, %1, %2;" : "=l"(d) : "l"(a), "l"(b)); return d;
}
__device__ __forceinline__ ull add2(ull a, ull b) {
    ull d; asm("add.rn.f32x2 %0, %1, %2;" : "=l"(d) : "l"(a), "l"(b)); return d;
}

// ---------------- cp.async helpers ----------------
__device__ __forceinline__ void cp_async16(unsigned s, const void* g) {
    asm volatile("cp.async.cg.shared.global [%0], [%1], 16;\n" :: "r"(s), "l"(g));
}
#define CP_COMMIT()  asm volatile("cp.async.commit_group;\n" ::: "memory")
#define CP_WAIT_1()  asm volatile("cp.async.wait_group 1;\n" ::: "memory")
#define CP_WAIT_0()  asm volatile("cp.async.wait_group 0;\n" ::: "memory")

// =================================================================
// Kernel A: q/k/v = W @ x + b   (x: [b][c][n], out: [b][n][c])
// grid (64, 2), 256 threads
// =================================================================
__global__ __launch_bounds__(256) void qkv_kernel(
    const float* __restrict__ x,
    const float* __restrict__ Wq, const float* __restrict__ bq,
    const float* __restrict__ Wk, const float* __restrict__ bk,
    const float* __restrict__ Wv, const float* __restrict__ bv)
{
    const int b  = blockIdx.y;
    const int n0 = blockIdx.x * 64;
    const int tid = threadIdx.x;

    __shared__ float xs[64][64];       // [c][n]
    __shared__ float Ws[3][64][65];    // padded weights [m][o][c]

    for (int i = tid; i < 64 * 16; i += 256) {
        int c = i >> 4, n4 = i & 15;
        float4 t = *(const float4*)(x + ((size_t)(b * C_ + c)) * N_ + n0 + n4 * 4);
        xs[c][n4*4+0] = t.x; xs[c][n4*4+1] = t.y; xs[c][n4*4+2] = t.z; xs[c][n4*4+3] = t.w;
    }
    for (int i = tid; i < 64 * 16; i += 256) {
        int o = i >> 4, c4 = i & 15;
        float4 tq = *(const float4*)(Wq + o * 64 + c4 * 4);
        float4 tk = *(const float4*)(Wk + o * 64 + c4 * 4);
        float4 tv = *(const float4*)(Wv + o * 64 + c4 * 4);
        Ws[0][o][c4*4+0]=tq.x; Ws[0][o][c4*4+1]=tq.y; Ws[0][o][c4*4+2]=tq.z; Ws[0][o][c4*4+3]=tq.w;
        Ws[1][o][c4*4+0]=tk.x; Ws[1][o][c4*4+1]=tk.y; Ws[1][o][c4*4+2]=tk.z; Ws[1][o][c4*4+3]=tk.w;
        Ws[2][o][c4*4+0]=tv.x; Ws[2][o][c4*4+1]=tv.y; Ws[2][o][c4*4+2]=tv.z; Ws[2][o][c4*4+3]=tv.w;
    }
    __syncthreads();

    const int nb = tid & 15;
    const int ob = tid >> 4;

    float acc[3][4][4];
    #pragma unroll
    for (int m = 0; m < 3; m++)
        #pragma unroll
        for (int i = 0; i < 4; i++)
            #pragma unroll
            for (int j = 0; j < 4; j++) acc[m][i][j] = 0.f;

    #pragma unroll 4
    for (int c = 0; c < 64; c++) {
        float xv[4];
        #pragma unroll
        for (int ni = 0; ni < 4; ni++) xv[ni] = xs[c][nb + 16 * ni];
        #pragma unroll
        for (int m = 0; m < 3; m++) {
            float wv[4];
            #pragma unroll
            for (int oi = 0; oi < 4; oi++) wv[oi] = Ws[m][ob * 4 + oi][c];
            #pragma unroll
            for (int oi = 0; oi < 4; oi++)
                #pragma unroll
                for (int ni = 0; ni < 4; ni++)
                    acc[m][oi][ni] = fmaf(wv[oi], xv[ni], acc[m][oi][ni]);
        }
    }

    float* outs[3] = { g_q, g_k, g_v };
    const float* biases[3] = { bq, bk, bv };
    #pragma unroll
    for (int m = 0; m < 3; m++) {
        float* dst = outs[m];
        #pragma unroll
        for (int oi = 0; oi < 4; oi++) {
            int o = ob * 4 + oi;
            float bias = biases[m][o];
            #pragma unroll
            for (int ni = 0; ni < 4; ni++) {
                int n = n0 + nb + 16 * ni;
                dst[((size_t)b * N_ + n) * C_ + o] = acc[m][oi][ni] + bias;
            }
        }
    }
}

// =================================================================
// Kernel B: flash attention v4 (key-split x4, 512 thr, f32x2, cp.async).
// grid (64, 2), 512 threads -> 4 warps/SMSP.
// Warp w handles range (w>>2), queries (w&3)*16..+16.
// Per warp: 16 queries, lane pair per query, 32 channels per lane,
// ONE shfl per key, broadcast LDS.
// =================================================================
__global__ __launch_bounds__(512, 1) void attn_kernel()
{
    extern __shared__ float dsm[];    // 64 KB: K [0,8192), V [8192,16384)

    const int b    = blockIdx.y;
    const int q0   = blockIdx.x * 64;
    const int tid  = threadIdx.x;
    const int warp = tid >> 5, lane = tid & 31;
    const int range = warp >> 2;                  // 0..3 (key quarter)
    const int qi    = (warp & 3) * 16 + (lane & 15);
    const int half  = lane >> 4;                  // 32-channel half

    const unsigned smem_u32 = (unsigned)__cvta_generic_to_shared(dsm);

    // q registers: 32 floats = 16 packed pairs
    ull q2[16];
    {
        const ull* qp = (const ull*)(g_q + ((size_t)b * N_ + q0 + qi) * C_ + half * 32);
        #pragma unroll
        for (int i = 0; i < 16; i++) q2[i] = qp[i];
    }
    ull o2[16];
    #pragma unroll
    for (int i = 0; i < 16; i++) o2[i] = 0ull;
    float mval = -1e30f, lsum = 0.f;

    const float* kbatch = g_k + (size_t)b * N_ * C_;
    const float* vbatch = g_v + (size_t)b * N_ * C_;

    // tile loader: K = 4 ranges x 16 keys x 64 floats (1024 float4),
    // V same. 2048 float4 total, 512 threads -> 4 each.
    // K region layout: [range][buf][KT*64] floats; V at +VOFF.
    auto load_tiles = [&](int t, int buf) {
        #pragma unroll
        for (int i = 0; i < 4; i++) {
            int e   = tid + 512 * i;          // 0..2047
            int isv = e >> 10;                // 0:K 1:V
            int er  = e & 1023;
            int r   = er >> 8;                // range
            int elem = er & 255;              // float4 within range tile
            const float* gbase = (isv ? vbatch : kbatch) +
                                 ((size_t)(r * KEYS_PER_RANGE + t * KT)) * 64;
            unsigned dst = (isv ? VOFF : 0) +
                           (unsigned)(r * 2 + buf) * (KT * 64) + elem * 4;
            cp_async16(smem_u32 + dst * 4, (const float4*)gbase + elem);
        }
        CP_COMMIT();
    };

    load_tiles(0, 0);

    for (int t = 0; t < NTILES; t++) {
        if (t + 1 < NTILES) { load_tiles(t + 1, (t + 1) & 1); CP_WAIT_1(); }
        else                { CP_WAIT_0(); }
        __syncthreads();

        const float* Kb = dsm + (range * 2 + (t & 1)) * (KT * 64) + half * 32;
        const float* Vb = Kb + VOFF;

        #pragma unroll 4
        for (int j = 0; j < KT; j++) {
            // K row: 32 floats = 8 LDS.128, broadcast within each half
            ull kv[16];
            {
                const ulonglong2* Kr = (const ulonglong2*)(Kb + j * 64);
                #pragma unroll
                for (int i2 = 0; i2 < 8; i2++) {
                    ulonglong2 tt = Kr[i2];
                    kv[2*i2] = tt.x; kv[2*i2+1] = tt.y;
                }
            }
            ull a0 = mul2(q2[0], kv[0]);
            ull a1 = mul2(q2[1], kv[1]);
            ull a2 = mul2(q2[2], kv[2]);
            ull a3 = mul2(q2[3], kv[3]);
            #pragma unroll
            for (int i2 = 1; i2 < 4; i2++) {
                a0 = fma2(q2[4*i2+0], kv[4*i2+0], a0);
                a1 = fma2(q2[4*i2+1], kv[4*i2+1], a1);
                a2 = fma2(q2[4*i2+2], kv[4*i2+2], a2);
                a3 = fma2(q2[4*i2+3], kv[4*i2+3], a3);
            }
            float2 sp = unpack2f(add2(add2(a0, a1), add2(a2, a3)));
            float s = sp.x + sp.y;
            s += __shfl_xor_sync(0xffffffffu, s, 16);   // one shfl per key

            if (s > mval) {                 // rare (~ln N per query)
                float sc = __expf(mval - s);
                mval = s;
                lsum *= sc;
                ull scp = pack2f(sc, sc);
                #pragma unroll
                for (int i = 0; i < 16; i++) o2[i] = mul2(o2[i], scp);
            }
            float p = __expf(s - mval);
            lsum += p;
            ull pp = pack2f(p, p);

            {
                const ulonglong2* Vr = (const ulonglong2*)(Vb + j * 64);
                #pragma unroll
                for (int i2 = 0; i2 < 8; i2++) {
                    ulonglong2 tt = Vr[i2];
                    o2[2*i2]   = fma2(pp, tt.x, o2[2*i2]);
                    o2[2*i2+1] = fma2(pp, tt.y, o2[2*i2+1]);
                }
            }
        }
        __syncthreads();   // all warps done with buf (t&1) before refill
    }

    // -------- 4-way merge: ranges 1..3 stage, range 0 combines -----------
    // overlay staging on dead tile smem (needs 13440 floats < 16384)
    float* So = dsm;                   // [3][64][68] padded
    float* Sm = dsm + 3 * 64 * 68;     // [3][64]
    float* Sl = Sm + 3 * 64;           // [3][64]

    if (range > 0) {
        ull* d2 = (ull*)(So + ((size_t)(range - 1) * 64 + qi) * 68 + half * 32);
        #pragma unroll
        for (int i = 0; i < 16; i++) d2[i] = o2[i];
        Sm[(range - 1) * 64 + qi] = mval;   // halves write same value
        Sl[(range - 1) * 64 + qi] = lsum;
    }
    __syncthreads();
    if (range == 0) {
        float m1 = Sm[qi], m2 = Sm[64 + qi], m3 = Sm[128 + qi];
        float l1 = Sl[qi], l2 = Sl[64 + qi], l3 = Sl[128 + qi];
        float mx = fmaxf(fmaxf(mval, m1), fmaxf(m2, m3));
        float f0 = __expf(mval - mx), f1 = __expf(m1 - mx);
        float f2 = __expf(m2 - mx),  f3 = __expf(m3 - mx);
        float l  = fmaf(lsum, f0, fmaf(l1, f1, fmaf(l2, f2, l3 * f3)));
        float inv = 1.f / l;
        ull c0 = pack2f(f0 * inv, f0 * inv);
        ull c1 = pack2f(f1 * inv, f1 * inv);
        ull c2 = pack2f(f2 * inv, f2 * inv);
        ull c3 = pack2f(f3 * inv, f3 * inv);
        const ull* s1 = (const ull*)(So + ((size_t)qi) * 68 + half * 32);
        const ull* s2 = (const ull*)(So + ((size_t)(64 + qi)) * 68 + half * 32);
        const ull* s3 = (const ull*)(So + ((size_t)(128 + qi)) * 68 + half * 32);
        ull* op = (ull*)(g_hh + ((size_t)b * N_ + q0 + qi) * C_ + half * 32);
        #pragma unroll
        for (int i = 0; i < 16; i++) {
            ull t = mul2(o2[i], c0);
            t = fma2(c1, s1[i], t);
            t = fma2(c2, s2[i], t);
            t = fma2(c3, s3[i], t);
            op[i] = t;
        }
    }
}

// =================================================================
// Kernel C: y = x + Wp @ hh + bp   (out layout [b][c][n])
// grid (32, 2), 256 threads, n-tile of 128
// =================================================================
__global__ __launch_bounds__(256) void proj_kernel(
    const float* __restrict__ x,
    const float* __restrict__ Wp, const float* __restrict__ bp)
{
    const int b  = blockIdx.y;
    const int n0 = blockIdx.x * 128;
    const int tid = threadIdx.x;

    __shared__ float hs[128][65];
    __shared__ float Wps[64][65];

    for (int i = tid; i < 128 * 16; i += 256) {
        int n = i >> 4, c4 = i & 15;
        float4 t = *(const float4*)(g_hh + ((size_t)b * N_ + n0 + n) * C_ + c4 * 4);
        hs[n][c4*4+0] = t.x; hs[n][c4*4+1] = t.y; hs[n][c4*4+2] = t.z; hs[n][c4*4+3] = t.w;
    }
    for (int i = tid; i < 64 * 16; i += 256) {
        int o = i >> 4, c4 = i & 15;
        float4 t = *(const float4*)(Wp + o * 64 + c4 * 4);
        Wps[o][c4*4+0] = t.x; Wps[o][c4*4+1] = t.y; Wps[o][c4*4+2] = t.z; Wps[o][c4*4+3] = t.w;
    }
    __syncthreads();

    const int nb = tid & 15;
    const int ob = tid >> 4;

    float acc[4][8];
    #pragma unroll
    for (int i = 0; i < 4; i++)
        #pragma unroll
        for (int j = 0; j < 8; j++) acc[i][j] = 0.f;

    #pragma unroll 4
    for (int c = 0; c < 64; c++) {
        float hv[8];
        #pragma unroll
        for (int j = 0; j < 8; j++) hv[j] = hs[nb + 16 * j][c];
        float wv[4];
        #pragma unroll
        for (int i = 0; i < 4; i++) wv[i] = Wps[ob * 4 + i][c];
        #pragma unroll
        for (int i = 0; i < 4; i++)
            #pragma unroll
            for (int j = 0; j < 8; j++)
                acc[i][j] = fmaf(wv[i], hv[j], acc[i][j]);
    }

    #pragma unroll
    for (int i = 0; i < 4; i++) {
        int o = ob * 4 + i;
        float bias = bp[o];
        #pragma unroll
        for (int j = 0; j < 8; j++) {
            int n = n0 + nb + 16 * j;
            size_t idx = ((size_t)(b * C_ + o)) * N_ + n;
            g_y[idx] = acc[i][j] + bias + x[idx];
        }
    }
}

// =================================================================
// Kernel D: GroupNorm(32) + Swish.  grid (32, 2), 256 threads.
// =================================================================
__global__ __launch_bounds__(256) void gnorm_kernel(
    const float* __restrict__ gamma, const float* __restrict__ beta,
    float* __restrict__ out)
{
    const int b = blockIdx.y, g = blockIdx.x;
    const int tid = threadIdx.x;
    const size_t base = ((size_t)(b * C_ + g * 2)) * N_;
    const float* yb = g_y + base;

    float vals[32];
    float s = 0.f, sq = 0.f;
    #pragma unroll
    for (int i = 0; i < 32; i++) {
        float v = yb[tid + 256 * i];
        vals[i] = v;
        s += v;
        sq = fmaf(v, v, sq);
    }
    #pragma unroll
    for (int off = 16; off; off >>= 1) {
        s  += __shfl_xor_sync(0xffffffffu, s,  off);
        sq += __shfl_xor_sync(0xffffffffu, sq, off);
    }
    __shared__ float red[16];
    if ((tid & 31) == 0) { red[tid >> 5] = s; red[8 + (tid >> 5)] = sq; }
    __syncthreads();
    float S  = red[0] + red[1] + red[2] + red[3] + red[4] + red[5] + red[6] + red[7];
    float SQ = red[8] + red[9] + red[10] + red[11] + red[12] + red[13] + red[14] + red[15];

    const float mean = S * (1.f / 8192.f);
    const float var  = SQ * (1.f / 8192.f) - mean * mean;
    const float rinv = rsqrtf(var + EPSV);

    const float g0 = gamma[g * 2], g1 = gamma[g * 2 + 1];
    const float b0 = beta[g * 2],  b1 = beta[g * 2 + 1];

    float* ob = out + base;
    #pragma unroll
    for (int i = 0; i < 32; i++) {
        int e = tid + 256 * i;
        float gm = (e < N_) ? g0 : g1;
        float bt = (e < N_) ? b0 : b1;
        float yn = (vals[i] - mean) * rinv * gm + bt;
        ob[e] = yn / (1.f + __expf(-yn));
    }
}

// =================================================================
extern "C" void kernel_launch(void* const* d_in, const int* in_sizes, int n_in,
                              void* d_out, int out_size)
{
    const float* x     = (const float*)d_in[0];
    const float* Wq    = (const float*)d_in[1];
    const float* bq    = (const float*)d_in[2];
    const float* Wk    = (const float*)d_in[3];
    const float* bk    = (const float*)d_in[4];
    const float* Wv    = (const float*)d_in[5];
    const float* bv    = (const float*)d_in[6];
    const float* Wp    = (const float*)d_in[7];
    const float* bp    = (const float*)d_in[8];
    const float* gamma = (const float*)d_in[9];
    const float* beta  = (const float*)d_in[10];
    float* out = (float*)d_out;

    cudaFuncSetAttribute(attn_kernel,
                         cudaFuncAttributeMaxDynamicSharedMemorySize, SMEM_BYTES);

    qkv_kernel<<<dim3(64, 2), 256>>>(x, Wq, bq, Wk, bk, Wv, bv);
    attn_kernel<<<dim3(64, 2), 512, SMEM_BYTES>>>();
    proj_kernel<<<dim3(32, 2), 256>>>(x, Wp, bp);
    gnorm_kernel<<<dim3(32, 2), 256>>>(gamma, beta, out);
}

// round 12
// speedup vs baseline: 3.3146x; 1.0159x over previous
#include <cuda_runtime.h>
#include <math.h>

#define B_  2
#define C_  64
#define N_  4096
#define EPSV 1e-5f

#define NRANGE  4                  // key ranges (warps 0-3, 4-7, 8-11, 12-15)
#define KEYS_PER_RANGE 1024
#define KT      16                 // keys per tile per range
#define NTILES  (KEYS_PER_RANGE / KT)   // 64
#define VOFF    8192               // float offset of V region in dyn smem
#define SMEM_BYTES (16384 * 4)     // 64 KB

typedef unsigned long long ull;

// ---------------- scratch (no allocation allowed) ----------------
__device__ float g_q [B_ * N_ * C_];   // [b][n][c]
__device__ float g_k [B_ * N_ * C_];   // [b][n][c]
__device__ float g_v [B_ * N_ * C_];   // [b][n][c]
__device__ float g_hh[B_ * N_ * C_];   // attention out, [b][n][c]
__device__ float g_y [B_ * C_ * N_];   // residual+proj, [b][c][n]

// ---------------- packed f32x2 helpers (sm_10x) ----------------
__device__ __forceinline__ ull pack2f(float lo, float hi) {
    ull r; asm("mov.b64 %0, {%1,%2};" : "=l"(r) : "f"(lo), "f"(hi)); return r;
}
__device__ __forceinline__ float2 unpack2f(ull v) {
    float2 r; asm("mov.b64 {%0,%1}, %2;" : "=f"(r.x), "=f"(r.y) : "l"(v)); return r;
}
__device__ __forceinline__ ull fma2(ull a, ull b, ull c) {
    ull d; asm("fma.rn.f32x2 %0, %1, %2, %3;" : "=l"(d) : "l"(a), "l"(b), "l"(c)); return d;
}
__device__ __forceinline__ ull mul2(ull a, ull b) {
    ull d; asm("mul.rn.f32x2 %0, %1, %2;" : "=l"(d) : "l"(a), "l"(b)); return d;
}
__device__ __forceinline__ ull add2(ull a, ull b) {
    ull d; asm("add.rn.f32x2 %0, %1, %2;" : "=l"(d) : "l"(a), "l"(b)); return d;
}

// ---------------- cp.async helpers ----------------
__device__ __forceinline__ void cp_async16(unsigned s, const void* g) {
    asm volatile("cp.async.cg.shared.global [%0], [%1], 16;\n" :: "r"(s), "l"(g));
}
#define CP_COMMIT()  asm volatile("cp.async.commit_group;\n" ::: "memory")
#define CP_WAIT_1()  asm volatile("cp.async.wait_group 1;\n" ::: "memory")
#define CP_WAIT_0()  asm volatile("cp.async.wait_group 0;\n" ::: "memory")

// =================================================================
// Kernel A: q/k/v = W @ x + b   (x: [b][c][n], out: [b][n][c])
// grid (64, 2), 256 threads
// =================================================================
__global__ __launch_bounds__(256) void qkv_kernel(
    const float* __restrict__ x,
    const float* __restrict__ Wq, const float* __restrict__ bq,
    const float* __restrict__ Wk, const float* __restrict__ bk,
    const float* __restrict__ Wv, const float* __restrict__ bv)
{
    const int b  = blockIdx.y;
    const int n0 = blockIdx.x * 64;
    const int tid = threadIdx.x;

    __shared__ float xs[64][64];       // [c][n]
    __shared__ float Ws[3][64][65];    // padded weights [m][o][c]

    for (int i = tid; i < 64 * 16; i += 256) {
        int c = i >> 4, n4 = i & 15;
        float4 t = *(const float4*)(x + ((size_t)(b * C_ + c)) * N_ + n0 + n4 * 4);
        xs[c][n4*4+0] = t.x; xs[c][n4*4+1] = t.y; xs[c][n4*4+2] = t.z; xs[c][n4*4+3] = t.w;
    }
    for (int i = tid; i < 64 * 16; i += 256) {
        int o = i >> 4, c4 = i & 15;
        float4 tq = *(const float4*)(Wq + o * 64 + c4 * 4);
        float4 tk = *(const float4*)(Wk + o * 64 + c4 * 4);
        float4 tv = *(const float4*)(Wv + o * 64 + c4 * 4);
        Ws[0][o][c4*4+0]=tq.x; Ws[0][o][c4*4+1]=tq.y; Ws[0][o][c4*4+2]=tq.z; Ws[0][o][c4*4+3]=tq.w;
        Ws[1][o][c4*4+0]=tk.x; Ws[1][o][c4*4+1]=tk.y; Ws[1][o][c4*4+2]=tk.z; Ws[1][o][c4*4+3]=tk.w;
        Ws[2][o][c4*4+0]=tv.x; Ws[2][o][c4*4+1]=tv.y; Ws[2][o][c4*4+2]=tv.z; Ws[2][o][c4*4+3]=tv.w;
    }
    __syncthreads();

    const int nb = tid & 15;
    const int ob = tid >> 4;

    float acc[3][4][4];
    #pragma unroll
    for (int m = 0; m < 3; m++)
        #pragma unroll
        for (int i = 0; i < 4; i++)
            #pragma unroll
            for (int j = 0; j < 4; j++) acc[m][i][j] = 0.f;

    #pragma unroll 4
    for (int c = 0; c < 64; c++) {
        float xv[4];
        #pragma unroll
        for (int ni = 0; ni < 4; ni++) xv[ni] = xs[c][nb + 16 * ni];
        #pragma unroll
        for (int m = 0; m < 3; m++) {
            float wv[4];
            #pragma unroll
            for (int oi = 0; oi < 4; oi++) wv[oi] = Ws[m][ob * 4 + oi][c];
            #pragma unroll
            for (int oi = 0; oi < 4; oi++)
                #pragma unroll
                for (int ni = 0; ni < 4; ni++)
                    acc[m][oi][ni] = fmaf(wv[oi], xv[ni], acc[m][oi][ni]);
        }
    }

    float* outs[3] = { g_q, g_k, g_v };
    const float* biases[3] = { bq, bk, bv };
    #pragma unroll
    for (int m = 0; m < 3; m++) {
        float* dst = outs[m];
        #pragma unroll
        for (int oi = 0; oi < 4; oi++) {
            int o = ob * 4 + oi;
            float bias = biases[m][o];
            #pragma unroll
            for (int ni = 0; ni < 4; ni++) {
                int n = n0 + nb + 16 * ni;
                dst[((size_t)b * N_ + n) * C_ + o] = acc[m][oi][ni] + bias;
            }
        }
    }
}

// =================================================================
// Kernel B: flash attention v5 (tile-batched softmax).
// grid (64, 2), 512 threads -> 4 warps/SMSP, key-split x4.
// Per warp: 16 queries, lane pair per query, 32 channels per lane.
// Per tile of 16 keys: Phase A computes all 16 scores (independent
// dot+shfl chains pipeline), Phase B one max-tree + at most one
// rescale, Phase C batched exp + PV accumulation. Exact flash algebra.
// =================================================================
__global__ __launch_bounds__(512, 1) void attn_kernel()
{
    extern __shared__ float dsm[];    // 64 KB: K [0,8192), V [8192,16384)

    const int b    = blockIdx.y;
    const int q0   = blockIdx.x * 64;
    const int tid  = threadIdx.x;
    const int warp = tid >> 5, lane = tid & 31;
    const int range = warp >> 2;                  // 0..3 (key quarter)
    const int qi    = (warp & 3) * 16 + (lane & 15);
    const int half  = lane >> 4;                  // 32-channel half

    const unsigned smem_u32 = (unsigned)__cvta_generic_to_shared(dsm);

    // q registers: 32 floats = 16 packed pairs
    ull q2[16];
    {
        const ull* qp = (const ull*)(g_q + ((size_t)b * N_ + q0 + qi) * C_ + half * 32);
        #pragma unroll
        for (int i = 0; i < 16; i++) q2[i] = qp[i];
    }
    ull o2[16];
    #pragma unroll
    for (int i = 0; i < 16; i++) o2[i] = 0ull;
    float mval = -1e30f, lsum = 0.f;

    const float* kbatch = g_k + (size_t)b * N_ * C_;
    const float* vbatch = g_v + (size_t)b * N_ * C_;

    auto load_tiles = [&](int t, int buf) {
        #pragma unroll
        for (int i = 0; i < 4; i++) {
            int e   = tid + 512 * i;          // 0..2047
            int isv = e >> 10;                // 0:K 1:V
            int er  = e & 1023;
            int r   = er >> 8;                // range
            int elem = er & 255;              // float4 within range tile
            const float* gbase = (isv ? vbatch : kbatch) +
                                 ((size_t)(r * KEYS_PER_RANGE + t * KT)) * 64;
            unsigned dst = (isv ? VOFF : 0) +
                           (unsigned)(r * 2 + buf) * (KT * 64) + elem * 4;
            cp_async16(smem_u32 + dst * 4, (const float4*)gbase + elem);
        }
        CP_COMMIT();
    };

    load_tiles(0, 0);

    for (int t = 0; t < NTILES; t++) {
        if (t + 1 < NTILES) { load_tiles(t + 1, (t + 1) & 1); CP_WAIT_1(); }
        else                { CP_WAIT_0(); }
        __syncthreads();

        const float* Kb = dsm + (range * 2 + (t & 1)) * (KT * 64) + half * 32;
        const float* Vb = Kb + VOFF;

        // ---------- Phase A: all 16 scores (independent chains) ----------
        float sreg[KT];
        #pragma unroll 4
        for (int j = 0; j < KT; j++) {
            const ulonglong2* Kr = (const ulonglong2*)(Kb + j * 64);
            ulonglong2 k0 = Kr[0], k1 = Kr[1], k2 = Kr[2], k3 = Kr[3];
            ull a0 = mul2(q2[0], k0.x);
            ull a1 = mul2(q2[1], k0.y);
            ull a2 = mul2(q2[2], k1.x);
            ull a3 = mul2(q2[3], k1.y);
            a0 = fma2(q2[4], k2.x, a0);
            a1 = fma2(q2[5], k2.y, a1);
            a2 = fma2(q2[6], k3.x, a2);
            a3 = fma2(q2[7], k3.y, a3);
            ulonglong2 k4 = Kr[4], k5 = Kr[5], k6 = Kr[6], k7 = Kr[7];
            a0 = fma2(q2[8],  k4.x, a0);
            a1 = fma2(q2[9],  k4.y, a1);
            a2 = fma2(q2[10], k5.x, a2);
            a3 = fma2(q2[11], k5.y, a3);
            a0 = fma2(q2[12], k6.x, a0);
            a1 = fma2(q2[13], k6.y, a1);
            a2 = fma2(q2[14], k7.x, a2);
            a3 = fma2(q2[15], k7.y, a3);
            float2 sp = unpack2f(add2(add2(a0, a1), add2(a2, a3)));
            float s = sp.x + sp.y;
            s += __shfl_xor_sync(0xffffffffu, s, 16);
            sreg[j] = s;
        }

        // ---------- Phase B: one max + at most one rescale per tile ------
        float tmax = fmaxf(sreg[0], sreg[1]);
        float tm1  = fmaxf(sreg[2], sreg[3]);
        float tm2  = fmaxf(sreg[4], sreg[5]);
        float tm3  = fmaxf(sreg[6], sreg[7]);
        float tm4  = fmaxf(sreg[8], sreg[9]);
        float tm5  = fmaxf(sreg[10], sreg[11]);
        float tm6  = fmaxf(sreg[12], sreg[13]);
        float tm7  = fmaxf(sreg[14], sreg[15]);
        tmax = fmaxf(fmaxf(fmaxf(tmax, tm1), fmaxf(tm2, tm3)),
                     fmaxf(fmaxf(tm4, tm5), fmaxf(tm6, tm7)));
        if (tmax > mval) {
            float sc = __expf(mval - tmax);
            mval = tmax;
            lsum *= sc;
            ull scp = pack2f(sc, sc);
            #pragma unroll
            for (int i = 0; i < 16; i++) o2[i] = mul2(o2[i], scp);
        }

        // ---------- Phase C: batched exp + PV ----------------------------
        float psum = 0.f;
        #pragma unroll 4
        for (int j = 0; j < KT; j++) {
            float p = __expf(sreg[j] - mval);
            psum += p;
            ull pp = pack2f(p, p);
            const ulonglong2* Vr = (const ulonglong2*)(Vb + j * 64);
            #pragma unroll
            for (int i2 = 0; i2 < 8; i2++) {
                ulonglong2 tt = Vr[i2];
                o2[2*i2]   = fma2(pp, tt.x, o2[2*i2]);
                o2[2*i2+1] = fma2(pp, tt.y, o2[2*i2+1]);
            }
        }
        lsum += psum;

        __syncthreads();   // all warps done with buf (t&1) before refill
    }

    // -------- 4-way merge: ranges 1..3 stage, range 0 combines -----------
    // overlay staging on dead tile smem (needs 13440 floats < 16384)
    float* So = dsm;                   // [3][64][68] padded
    float* Sm = dsm + 3 * 64 * 68;     // [3][64]
    float* Sl = Sm + 3 * 64;           // [3][64]

    if (range > 0) {
        ull* d2 = (ull*)(So + ((size_t)(range - 1) * 64 + qi) * 68 + half * 32);
        #pragma unroll
        for (int i = 0; i < 16; i++) d2[i] = o2[i];
        Sm[(range - 1) * 64 + qi] = mval;   // halves write same value
        Sl[(range - 1) * 64 + qi] = lsum;
    }
    __syncthreads();
    if (range == 0) {
        float m1 = Sm[qi], m2 = Sm[64 + qi], m3 = Sm[128 + qi];
        float l1 = Sl[qi], l2 = Sl[64 + qi], l3 = Sl[128 + qi];
        float mx = fmaxf(fmaxf(mval, m1), fmaxf(m2, m3));
        float f0 = __expf(mval - mx), f1 = __expf(m1 - mx);
        float f2 = __expf(m2 - mx),  f3 = __expf(m3 - mx);
        float l  = fmaf(lsum, f0, fmaf(l1, f1, fmaf(l2, f2, l3 * f3)));
        float inv = 1.f / l;
        ull c0 = pack2f(f0 * inv, f0 * inv);
        ull c1 = pack2f(f1 * inv, f1 * inv);
        ull c2 = pack2f(f2 * inv, f2 * inv);
        ull c3 = pack2f(f3 * inv, f3 * inv);
        const ull* s1 = (const ull*)(So + ((size_t)qi) * 68 + half * 32);
        const ull* s2 = (const ull*)(So + ((size_t)(64 + qi)) * 68 + half * 32);
        const ull* s3 = (const ull*)(So + ((size_t)(128 + qi)) * 68 + half * 32);
        ull* op = (ull*)(g_hh + ((size_t)b * N_ + q0 + qi) * C_ + half * 32);
        #pragma unroll
        for (int i = 0; i < 16; i++) {
            ull t = mul2(o2[i], c0);
            t = fma2(c1, s1[i], t);
            t = fma2(c2, s2[i], t);
            t = fma2(c3, s3[i], t);
            op[i] = t;
        }
    }
}

// =================================================================
// Kernel C: y = x + Wp @ hh + bp   (out layout [b][c][n])
// grid (32, 2), 256 threads, n-tile of 128
// =================================================================
__global__ __launch_bounds__(256) void proj_kernel(
    const float* __restrict__ x,
    const float* __restrict__ Wp, const float* __restrict__ bp)
{
    const int b  = blockIdx.y;
    const int n0 = blockIdx.x * 128;
    const int tid = threadIdx.x;

    __shared__ float hs[128][65];
    __shared__ float Wps[64][65];

    for (int i = tid; i < 128 * 16; i += 256) {
        int n = i >> 4, c4 = i & 15;
        float4 t = *(const float4*)(g_hh + ((size_t)b * N_ + n0 + n) * C_ + c4 * 4);
        hs[n][c4*4+0] = t.x; hs[n][c4*4+1] = t.y; hs[n][c4*4+2] = t.z; hs[n][c4*4+3] = t.w;
    }
    for (int i = tid; i < 64 * 16; i += 256) {
        int o = i >> 4, c4 = i & 15;
        float4 t = *(const float4*)(Wp + o * 64 + c4 * 4);
        Wps[o][c4*4+0] = t.x; Wps[o][c4*4+1] = t.y; Wps[o][c4*4+2] = t.z; Wps[o][c4*4+3] = t.w;
    }
    __syncthreads();

    const int nb = tid & 15;
    const int ob = tid >> 4;

    float acc[4][8];
    #pragma unroll
    for (int i = 0; i < 4; i++)
        #pragma unroll
        for (int j = 0; j < 8; j++) acc[i][j] = 0.f;

    #pragma unroll 4
    for (int c = 0; c < 64; c++) {
        float hv[8];
        #pragma unroll
        for (int j = 0; j < 8; j++) hv[j] = hs[nb + 16 * j][c];
        float wv[4];
        #pragma unroll
        for (int i = 0; i < 4; i++) wv[i] = Wps[ob * 4 + i][c];
        #pragma unroll
        for (int i = 0; i < 4; i++)
            #pragma unroll
            for (int j = 0; j < 8; j++)
                acc[i][j] = fmaf(wv[i], hv[j], acc[i][j]);
    }

    #pragma unroll
    for (int i = 0; i < 4; i++) {
        int o = ob * 4 + i;
        float bias = bp[o];
        #pragma unroll
        for (int j = 0; j < 8; j++) {
            int n = n0 + nb + 16 * j;
            size_t idx = ((size_t)(b * C_ + o)) * N_ + n;
            g_y[idx] = acc[i][j] + bias + x[idx];
        }
    }
}

// =================================================================
// Kernel D: GroupNorm(32) + Swish.  grid (32, 2), 256 threads.
// =================================================================
__global__ __launch_bounds__(256) void gnorm_kernel(
    const float* __restrict__ gamma, const float* __restrict__ beta,
    float* __restrict__ out)
{
    const int b = blockIdx.y, g = blockIdx.x;
    const int tid = threadIdx.x;
    const size_t base = ((size_t)(b * C_ + g * 2)) * N_;
    const float* yb = g_y + base;

    float vals[32];
    float s = 0.f, sq = 0.f;
    #pragma unroll
    for (int i = 0; i < 32; i++) {
        float v = yb[tid + 256 * i];
        vals[i] = v;
        s += v;
        sq = fmaf(v, v, sq);
    }
    #pragma unroll
    for (int off = 16; off; off >>= 1) {
        s  += __shfl_xor_sync(0xffffffffu, s,  off);
        sq += __shfl_xor_sync(0xffffffffu, sq, off);
    }
    __shared__ float red[16];
    if ((tid & 31) == 0) { red[tid >> 5] = s; red[8 + (tid >> 5)] = sq; }
    __syncthreads();
    float S  = red[0] + red[1] + red[2] + red[3] + red[4] + red[5] + red[6] + red[7];
    float SQ = red[8] + red[9] + red[10] + red[11] + red[12] + red[13] + red[14] + red[15];

    const float mean = S * (1.f / 8192.f);
    const float var  = SQ * (1.f / 8192.f) - mean * mean;
    const float rinv = rsqrtf(var + EPSV);

    const float g0 = gamma[g * 2], g1 = gamma[g * 2 + 1];
    const float b0 = beta[g * 2],  b1 = beta[g * 2 + 1];

    float* ob = out + base;
    #pragma unroll
    for (int i = 0; i < 32; i++) {
        int e = tid + 256 * i;
        float gm = (e < N_) ? g0 : g1;
        float bt = (e < N_) ? b0 : b1;
        float yn = (vals[i] - mean) * rinv * gm + bt;
        ob[e] = yn / (1.f + __expf(-yn));
    }
}

// =================================================================
extern "C" void kernel_launch(void* const* d_in, const int* in_sizes, int n_in,
                              void* d_out, int out_size)
{
    const float* x     = (const float*)d_in[0];
    const float* Wq    = (const float*)d_in[1];
    const float* bq    = (const float*)d_in[2];
    const float* Wk    = (const float*)d_in[3];
    const float* bk    = (const float*)d_in[4];
    const float* Wv    = (const float*)d_in[5];
    const float* bv    = (const float*)d_in[6];
    const float* Wp    = (const float*)d_in[7];
    const float* bp    = (const float*)d_in[8];
    const float* gamma = (const float*)d_in[9];
    const float* beta  = (const float*)d_in[10];
    float* out = (float*)d_out;

    cudaFuncSetAttribute(attn_kernel,
                         cudaFuncAttributeMaxDynamicSharedMemorySize, SMEM_BYTES);

    qkv_kernel<<<dim3(64, 2), 256>>>(x, Wq, bq, Wk, bk, Wv, bv);
    attn_kernel<<<dim3(64, 2), 512, SMEM_BYTES>>>();
    proj_kernel<<<dim3(32, 2), 256>>>(x, Wp, bp);
    gnorm_kernel<<<dim3(32, 2), 256>>>(gamma, beta, out);
}

// round 14
// speedup vs baseline: 14.9459x; 4.5091x over previous
#include <cuda_runtime.h>
#include <cuda_bf16.h>
#include <math.h>

#define B_  2
#define C_  64
#define N_  4096
#define EPSV 1e-5f

// attention tiling
#define KT      32                 // keys per tile per range
#define NTILES  (2048 / KT)        // 64 iterations
#define K_STRIDE   144             // bytes per key row in smem (72 bf16)
#define V_STRIDE   80              // bytes per ch row in smem (40 bf16)
#define K_TILE_B   (KT * K_STRIDE)         // 4608
#define V_TILE_B   (64 * V_STRIDE)         // 5120
#define V_BASE_B   (4 * K_TILE_B)          // 18432
#define SMEM_BYTES (V_BASE_B + 4 * V_TILE_B)   // 38912

typedef unsigned long long ull;
typedef unsigned int u32;

// ---------------- scratch (no allocation allowed) ----------------
__device__ __nv_bfloat16 g_qh[B_ * N_ * C_];   // [b][n][c]
__device__ __nv_bfloat16 g_kh[B_ * N_ * C_];   // [b][n][c]
__device__ __nv_bfloat16 g_vt[B_ * C_ * N_];   // [b][c][n]  (transposed V)
__device__ float g_hh[B_ * N_ * C_];           // attention out, [b][n][c]
__device__ float g_y [B_ * C_ * N_];           // residual+proj, [b][c][n]

// ---------------- helpers ----------------
__device__ __forceinline__ u32 cvt2(float hi, float lo) {   // pack (hi,lo) -> bf16x2
    u32 r; asm("cvt.rn.bf16x2.f32 %0, %1, %2;" : "=r"(r) : "f"(hi), "f"(lo)); return r;
}
__device__ __forceinline__ void mma_bf16(float c[4], u32 a0, u32 a1, u32 a2, u32 a3,
                                         u32 b0, u32 b1) {
    asm volatile(
        "mma.sync.aligned.m16n8k16.row.col.f32.bf16.bf16.f32 "
        "{%0,%1,%2,%3},{%4,%5,%6,%7},{%8,%9},{%0,%1,%2,%3};"
        : "+f"(c[0]), "+f"(c[1]), "+f"(c[2]), "+f"(c[3])
        : "r"(a0), "r"(a1), "r"(a2), "r"(a3), "r"(b0), "r"(b1));
}
__device__ __forceinline__ void cp_async16(unsigned s, const void* g) {
    asm volatile("cp.async.cg.shared.global [%0], [%1], 16;\n" :: "r"(s), "l"(g));
}
#define CP_COMMIT()  asm volatile("cp.async.commit_group;\n" ::: "memory")
#define CP_WAIT_1()  asm volatile("cp.async.wait_group 1;\n" ::: "memory")
#define CP_WAIT_0()  asm volatile("cp.async.wait_group 0;\n" ::: "memory")

// =================================================================
// Kernel A: q/k/v projections -> bf16 (q,k: [b][n][c]; v: [b][c][n])
// grid (64, 2), 256 threads
// =================================================================
__global__ __launch_bounds__(256) void qkv_kernel(
    const float* __restrict__ x,
    const float* __restrict__ Wq, const float* __restrict__ bq,
    const float* __restrict__ Wk, const float* __restrict__ bk,
    const float* __restrict__ Wv, const float* __restrict__ bv)
{
    const int b  = blockIdx.y;
    const int n0 = blockIdx.x * 64;
    const int tid = threadIdx.x;

    __shared__ float xs[64][64];       // [c][n]
    __shared__ float Ws[3][64][65];    // padded weights [m][o][c]

    for (int i = tid; i < 64 * 16; i += 256) {
        int c = i >> 4, n4 = i & 15;
        float4 t = *(const float4*)(x + ((size_t)(b * C_ + c)) * N_ + n0 + n4 * 4);
        xs[c][n4*4+0] = t.x; xs[c][n4*4+1] = t.y; xs[c][n4*4+2] = t.z; xs[c][n4*4+3] = t.w;
    }
    for (int i = tid; i < 64 * 16; i += 256) {
        int o = i >> 4, c4 = i & 15;
        float4 tq = *(const float4*)(Wq + o * 64 + c4 * 4);
        float4 tk = *(const float4*)(Wk + o * 64 + c4 * 4);
        float4 tv = *(const float4*)(Wv + o * 64 + c4 * 4);
        Ws[0][o][c4*4+0]=tq.x; Ws[0][o][c4*4+1]=tq.y; Ws[0][o][c4*4+2]=tq.z; Ws[0][o][c4*4+3]=tq.w;
        Ws[1][o][c4*4+0]=tk.x; Ws[1][o][c4*4+1]=tk.y; Ws[1][o][c4*4+2]=tk.z; Ws[1][o][c4*4+3]=tk.w;
        Ws[2][o][c4*4+0]=tv.x; Ws[2][o][c4*4+1]=tv.y; Ws[2][o][c4*4+2]=tv.z; Ws[2][o][c4*4+3]=tv.w;
    }
    __syncthreads();

    const int nb = tid & 15;   // n = n0 + nb + 16*ni
    const int ob = tid >> 4;   // o = ob*4 + oi

    float acc[3][4][4];
    #pragma unroll
    for (int m = 0; m < 3; m++)
        #pragma unroll
        for (int i = 0; i < 4; i++)
            #pragma unroll
            for (int j = 0; j < 4; j++) acc[m][i][j] = 0.f;

    #pragma unroll 4
    for (int c = 0; c < 64; c++) {
        float xv[4];
        #pragma unroll
        for (int ni = 0; ni < 4; ni++) xv[ni] = xs[c][nb + 16 * ni];
        #pragma unroll
        for (int m = 0; m < 3; m++) {
            float wv[4];
            #pragma unroll
            for (int oi = 0; oi < 4; oi++) wv[oi] = Ws[m][ob * 4 + oi][c];
            #pragma unroll
            for (int oi = 0; oi < 4; oi++)
                #pragma unroll
                for (int ni = 0; ni < 4; ni++)
                    acc[m][oi][ni] = fmaf(wv[oi], xv[ni], acc[m][oi][ni]);
        }
    }

    // add bias
    const float* biases[3] = { bq, bk, bv };
    #pragma unroll
    for (int m = 0; m < 3; m++)
        #pragma unroll
        for (int oi = 0; oi < 4; oi++) {
            float bias = biases[m][ob * 4 + oi];
            #pragma unroll
            for (int ni = 0; ni < 4; ni++) acc[m][oi][ni] += bias;
        }

    // q,k -> bf16 [b][n][c]; pack 4 consecutive channels per store
    __nv_bfloat16* qk_out[2] = { g_qh, g_kh };
    #pragma unroll
    for (int m = 0; m < 2; m++) {
        #pragma unroll
        for (int ni = 0; ni < 4; ni++) {
            int n = n0 + nb + 16 * ni;
            u32 lo = cvt2(acc[m][1][ni], acc[m][0][ni]);
            u32 hi = cvt2(acc[m][3][ni], acc[m][2][ni]);
            uint2 pk; pk.x = lo; pk.y = hi;
            *(uint2*)(qk_out[m] + ((size_t)(b * N_ + n)) * C_ + ob * 4) = pk;
        }
    }
    // v -> bf16 transposed [b][c][n] (scattered 16-bit stores)
    #pragma unroll
    for (int oi = 0; oi < 4; oi++) {
        int o = ob * 4 + oi;
        #pragma unroll
        for (int ni = 0; ni < 4; ni++) {
            int n = n0 + nb + 16 * ni;
            g_vt[((size_t)(b * C_ + o)) * N_ + n] = __float2bfloat16(acc[2][oi][ni]);
        }
    }
}

// =================================================================
// Kernel B: flash attention v6 — bf16 mma.sync (m16n8k16).
// grid (64, 2), 256 threads = 8 warps = 4 qgroups x 2 key-ranges.
// Warp: 16 queries x 2048 keys (kg range), tiles of 32 keys.
// =================================================================
__global__ __launch_bounds__(256, 1) void attn_kernel()
{
    extern __shared__ char dsm[];

    const int b    = blockIdx.y;
    const int q0   = blockIdx.x * 64;
    const int tid  = threadIdx.x;
    const int warp = tid >> 5, lane = tid & 31;
    const int kg   = warp >> 2;        // key range 0/1 (2048 keys each)
    const int qg   = warp & 3;         // query group *16
    const int gid  = lane >> 2;        // 0..7
    const int thr  = lane & 3;         // 0..3

    const unsigned smem_u32 = (unsigned)__cvta_generic_to_shared(dsm);

    // ---- Q fragments (resident): qa[kstep][0..3] --------------------
    u32 qa[4][4];
    {
        const __nv_bfloat16* qb = g_qh + ((size_t)(b * N_ + q0 + qg * 16)) * C_;
        #pragma unroll
        for (int s = 0; s < 4; s++) {
            int col = 16 * s + 2 * thr;
            qa[s][0] = *(const u32*)(qb + gid * 64 + col);
            qa[s][1] = *(const u32*)(qb + (gid + 8) * 64 + col);
            qa[s][2] = *(const u32*)(qb + gid * 64 + col + 8);
            qa[s][3] = *(const u32*)(qb + (gid + 8) * 64 + col + 8);
        }
    }

    float o[8][4];
    #pragma unroll
    for (int i = 0; i < 8; i++)
        #pragma unroll
        for (int j = 0; j < 4; j++) o[i][j] = 0.f;
    float m0 = -1e30f, m1 = -1e30f, l0 = 0.f, l1 = 0.f;

    const __nv_bfloat16* kbat = g_kh + (size_t)b * N_ * C_;
    const __nv_bfloat16* vbat = g_vt + (size_t)b * C_ * N_;

    // ---- tile loader: K (both ranges) + Vt (both ranges) ------------
    auto load_tiles = [&](int t, int buf) {
        #pragma unroll
        for (int i = 0; i < 4; i++) {
            int e = tid + 256 * i;               // 0..1023
            if (e < 512) {                       // K: r(2) x key(32) x chunk(8)
                int r = e >> 8, key = (e >> 3) & 31, ck = e & 7;
                const void* src = kbat + ((size_t)(r * 2048 + t * KT + key)) * 64 + ck * 8;
                unsigned dst = (unsigned)((r * 2 + buf) * K_TILE_B + key * K_STRIDE + ck * 16);
                cp_async16(smem_u32 + dst, src);
            } else {                             // Vt: r(2) x ch(64) x chunk(4)
                int e2 = e - 512;
                int r = e2 >> 8, ch = (e2 >> 2) & 63, ck = e2 & 3;
                const void* src = vbat + ((size_t)ch) * N_ + r * 2048 + t * KT + ck * 8;
                unsigned dst = (unsigned)(V_BASE_B + (r * 2 + buf) * V_TILE_B + ch * V_STRIDE + ck * 16);
                cp_async16(smem_u32 + dst, src);
            }
        }
        CP_COMMIT();
    };

    load_tiles(0, 0);

    for (int t = 0; t < NTILES; t++) {
        if (t + 1 < NTILES) { load_tiles(t + 1, (t + 1) & 1); CP_WAIT_1(); }
        else                { CP_WAIT_0(); }
        __syncthreads();

        const int buf = t & 1;
        const char* Kb = dsm + (kg * 2 + buf) * K_TILE_B;
        const char* Vb = dsm + V_BASE_B + (kg * 2 + buf) * V_TILE_B;

        // ---- S = Q K^T : 4 n8-tiles x 4 ksteps ----------------------
        float c[4][4];
        #pragma unroll
        for (int t4 = 0; t4 < 4; t4++)
            #pragma unroll
            for (int j = 0; j < 4; j++) c[t4][j] = 0.f;

        #pragma unroll
        for (int t4 = 0; t4 < 4; t4++) {
            const char* krow = Kb + (8 * t4 + gid) * K_STRIDE + 4 * thr; // (2*thr)*2B
            #pragma unroll
            for (int s = 0; s < 4; s++) {
                u32 b0 = *(const u32*)(krow + 32 * s);
                u32 b1 = *(const u32*)(krow + 32 * s + 16);
                mma_bf16(c[t4], qa[s][0], qa[s][1], qa[s][2], qa[s][3], b0, b1);
            }
        }

        // ---- softmax (rows gid, gid+8) ------------------------------
        float tx0 = fmaxf(fmaxf(c[0][0], c[0][1]), fmaxf(c[1][0], c[1][1]));
        tx0 = fmaxf(tx0, fmaxf(fmaxf(c[2][0], c[2][1]), fmaxf(c[3][0], c[3][1])));
        float tx1 = fmaxf(fmaxf(c[0][2], c[0][3]), fmaxf(c[1][2], c[1][3]));
        tx1 = fmaxf(tx1, fmaxf(fmaxf(c[2][2], c[2][3]), fmaxf(c[3][2], c[3][3])));
        tx0 = fmaxf(tx0, __shfl_xor_sync(0xffffffffu, tx0, 1));
        tx0 = fmaxf(tx0, __shfl_xor_sync(0xffffffffu, tx0, 2));
        tx1 = fmaxf(tx1, __shfl_xor_sync(0xffffffffu, tx1, 1));
        tx1 = fmaxf(tx1, __shfl_xor_sync(0xffffffffu, tx1, 2));

        float mn0 = fmaxf(m0, tx0), mn1 = fmaxf(m1, tx1);
        float f0 = __expf(m0 - mn0), f1 = __expf(m1 - mn1);
        m0 = mn0; m1 = mn1;
        #pragma unroll
        for (int c8 = 0; c8 < 8; c8++) {
            o[c8][0] *= f0; o[c8][1] *= f0;
            o[c8][2] *= f1; o[c8][3] *= f1;
        }

        float p[4][4];
        float ps0 = 0.f, ps1 = 0.f;
        #pragma unroll
        for (int t4 = 0; t4 < 4; t4++) {
            p[t4][0] = __expf(c[t4][0] - m0);
            p[t4][1] = __expf(c[t4][1] - m0);
            p[t4][2] = __expf(c[t4][2] - m1);
            p[t4][3] = __expf(c[t4][3] - m1);
            ps0 += p[t4][0] + p[t4][1];
            ps1 += p[t4][2] + p[t4][3];
        }
        ps0 += __shfl_xor_sync(0xffffffffu, ps0, 1);
        ps0 += __shfl_xor_sync(0xffffffffu, ps0, 2);
        ps1 += __shfl_xor_sync(0xffffffffu, ps1, 1);
        ps1 += __shfl_xor_sync(0xffffffffu, ps1, 2);
        l0 = l0 * f0 + ps0;
        l1 = l1 * f1 + ps1;

        // ---- P fragments (bf16) ------------------------------------
        u32 pa[2][4];
        #pragma unroll
        for (int s = 0; s < 2; s++) {
            pa[s][0] = cvt2(p[2*s][1],   p[2*s][0]);
            pa[s][1] = cvt2(p[2*s][3],   p[2*s][2]);
            pa[s][2] = cvt2(p[2*s+1][1], p[2*s+1][0]);
            pa[s][3] = cvt2(p[2*s+1][3], p[2*s+1][2]);
        }

        // ---- O += P V : 8 ch-tiles x 2 ksteps -----------------------
        #pragma unroll
        for (int c8 = 0; c8 < 8; c8++) {
            const char* vrow = Vb + (8 * c8 + gid) * V_STRIDE + 4 * thr;
            #pragma unroll
            for (int s = 0; s < 2; s++) {
                u32 b0 = *(const u32*)(vrow + 32 * s);
                u32 b1 = *(const u32*)(vrow + 32 * s + 16);
                mma_bf16(o[c8], pa[s][0], pa[s][1], pa[s][2], pa[s][3], b0, b1);
            }
        }

        __syncthreads();   // all warps done with buf before refill
    }

    // -------- 2-way merge (kg1 stages, kg0 combines + writes) --------
    float* So = (float*)dsm;            // [64 q][66 ch]
    float* Sm = So + 64 * 66;           // [64]
    float* Sl = Sm + 64;                // [64]

    __syncthreads();
    const int qrow = qg * 16 + gid;
    if (kg == 1) {
        #pragma unroll
        for (int c8 = 0; c8 < 8; c8++) {
            int ch = 8 * c8 + 2 * thr;
            So[qrow * 66 + ch]       = o[c8][0];
            So[qrow * 66 + ch + 1]   = o[c8][1];
            So[(qrow+8) * 66 + ch]   = o[c8][2];
            So[(qrow+8) * 66 + ch+1] = o[c8][3];
        }
        if (thr == 0) {
            Sm[qrow] = m0;  Sm[qrow + 8] = m1;
            Sl[qrow] = l0;  Sl[qrow + 8] = l1;
        }
    }
    __syncthreads();
    if (kg == 0) {
        float mB0 = Sm[qrow], mB1 = Sm[qrow + 8];
        float lB0 = Sl[qrow], lB1 = Sl[qrow + 8];
        float mx0 = fmaxf(m0, mB0), mx1 = fmaxf(m1, mB1);
        float fa0 = __expf(m0 - mx0), fb0 = __expf(mB0 - mx0);
        float fa1 = __expf(m1 - mx1), fb1 = __expf(mB1 - mx1);
        float inv0 = 1.f / fmaf(l0, fa0, lB0 * fb0);
        float inv1 = 1.f / fmaf(l1, fa1, lB1 * fb1);
        float ca0 = fa0 * inv0, cb0 = fb0 * inv0;
        float ca1 = fa1 * inv1, cb1 = fb1 * inv1;

        float* hh0 = g_hh + ((size_t)(b * N_ + q0 + qrow)) * C_;
        float* hh1 = g_hh + ((size_t)(b * N_ + q0 + qrow + 8)) * C_;
        #pragma unroll
        for (int c8 = 0; c8 < 8; c8++) {
            int ch = 8 * c8 + 2 * thr;
            float2 r0, r1;
            r0.x = fmaf(o[c8][0], ca0, So[qrow * 66 + ch]     * cb0);
            r0.y = fmaf(o[c8][1], ca0, So[qrow * 66 + ch + 1] * cb0);
            r1.x = fmaf(o[c8][2], ca1, So[(qrow+8) * 66 + ch]     * cb1);
            r1.y = fmaf(o[c8][3], ca1, So[(qrow+8) * 66 + ch + 1] * cb1);
            *(float2*)(hh0 + ch) = r0;
            *(float2*)(hh1 + ch) = r1;
        }
    }
}

// =================================================================
// Kernel C: y = x + Wp @ hh + bp   (out layout [b][c][n])
// grid (32, 2), 256 threads, n-tile of 128
// =================================================================
__global__ __launch_bounds__(256) void proj_kernel(
    const float* __restrict__ x,
    const float* __restrict__ Wp, const float* __restrict__ bp)
{
    const int b  = blockIdx.y;
    const int n0 = blockIdx.x * 128;
    const int tid = threadIdx.x;

    __shared__ float hs[128][65];
    __shared__ float Wps[64][65];

    for (int i = tid; i < 128 * 16; i += 256) {
        int n = i >> 4, c4 = i & 15;
        float4 t = *(const float4*)(g_hh + ((size_t)b * N_ + n0 + n) * C_ + c4 * 4);
        hs[n][c4*4+0] = t.x; hs[n][c4*4+1] = t.y; hs[n][c4*4+2] = t.z; hs[n][c4*4+3] = t.w;
    }
    for (int i = tid; i < 64 * 16; i += 256) {
        int o = i >> 4, c4 = i & 15;
        float4 t = *(const float4*)(Wp + o * 64 + c4 * 4);
        Wps[o][c4*4+0] = t.x; Wps[o][c4*4+1] = t.y; Wps[o][c4*4+2] = t.z; Wps[o][c4*4+3] = t.w;
    }
    __syncthreads();

    const int nb = tid & 15;
    const int ob = tid >> 4;

    float acc[4][8];
    #pragma unroll
    for (int i = 0; i < 4; i++)
        #pragma unroll
        for (int j = 0; j < 8; j++) acc[i][j] = 0.f;

    #pragma unroll 4
    for (int c = 0; c < 64; c++) {
        float hv[8];
        #pragma unroll
        for (int j = 0; j < 8; j++) hv[j] = hs[nb + 16 * j][c];
        float wv[4];
        #pragma unroll
        for (int i = 0; i < 4; i++) wv[i] = Wps[ob * 4 + i][c];
        #pragma unroll
        for (int i = 0; i < 4; i++)
            #pragma unroll
            for (int j = 0; j < 8; j++)
                acc[i][j] = fmaf(wv[i], hv[j], acc[i][j]);
    }

    #pragma unroll
    for (int i = 0; i < 4; i++) {
        int o = ob * 4 + i;
        float bias = bp[o];
        #pragma unroll
        for (int j = 0; j < 8; j++) {
            int n = n0 + nb + 16 * j;
            size_t idx = ((size_t)(b * C_ + o)) * N_ + n;
            g_y[idx] = acc[i][j] + bias + x[idx];
        }
    }
}

// =================================================================
// Kernel D: GroupNorm(32) + Swish.  grid (32, 2), 256 threads.
// =================================================================
__global__ __launch_bounds__(256) void gnorm_kernel(
    const float* __restrict__ gamma, const float* __restrict__ beta,
    float* __restrict__ out)
{
    const int b = blockIdx.y, g = blockIdx.x;
    const int tid = threadIdx.x;
    const size_t base = ((size_t)(b * C_ + g * 2)) * N_;
    const float* yb = g_y + base;

    float vals[32];
    float s = 0.f, sq = 0.f;
    #pragma unroll
    for (int i = 0; i < 32; i++) {
        float v = yb[tid + 256 * i];
        vals[i] = v;
        s += v;
        sq = fmaf(v, v, sq);
    }
    #pragma unroll
    for (int off = 16; off; off >>= 1) {
        s  += __shfl_xor_sync(0xffffffffu, s,  off);
        sq += __shfl_xor_sync(0xffffffffu, sq, off);
    }
    __shared__ float red[16];
    if ((tid & 31) == 0) { red[tid >> 5] = s; red[8 + (tid >> 5)] = sq; }
    __syncthreads();
    float S  = red[0] + red[1] + red[2] + red[3] + red[4] + red[5] + red[6] + red[7];
    float SQ = red[8] + red[9] + red[10] + red[11] + red[12] + red[13] + red[14] + red[15];

    const float mean = S * (1.f / 8192.f);
    const float var  = SQ * (1.f / 8192.f) - mean * mean;
    const float rinv = rsqrtf(var + EPSV);

    const float g0 = gamma[g * 2], g1 = gamma[g * 2 + 1];
    const float b0 = beta[g * 2],  b1 = beta[g * 2 + 1];

    float* ob = out + base;
    #pragma unroll
    for (int i = 0; i < 32; i++) {
        int e = tid + 256 * i;
        float gm = (e < N_) ? g0 : g1;
        float bt = (e < N_) ? b0 : b1;
        float yn = (vals[i] - mean) * rinv * gm + bt;
        ob[e] = yn / (1.f + __expf(-yn));
    }
}

// =================================================================
extern "C" void kernel_launch(void* const* d_in, const int* in_sizes, int n_in,
                              void* d_out, int out_size)
{
    const float* x     = (const float*)d_in[0];
    const float* Wq    = (const float*)d_in[1];
    const float* bq    = (const float*)d_in[2];
    const float* Wk    = (const float*)d_in[3];
    const float* bk    = (const float*)d_in[4];
    const float* Wv    = (const float*)d_in[5];
    const float* bv    = (const float*)d_in[6];
    const float* Wp    = (const float*)d_in[7];
    const float* bp    = (const float*)d_in[8];
    const float* gamma = (const float*)d_in[9];
    const float* beta  = (const float*)d_in[10];
    float* out = (float*)d_out;

    cudaFuncSetAttribute(attn_kernel,
                         cudaFuncAttributeMaxDynamicSharedMemorySize, SMEM_BYTES);

    qkv_kernel<<<dim3(64, 2), 256>>>(x, Wq, bq, Wk, bk, Wv, bv);
    attn_kernel<<<dim3(64, 2), 256, SMEM_BYTES>>>();
    proj_kernel<<<dim3(32, 2), 256>>>(x, Wp, bp);
    gnorm_kernel<<<dim3(32, 2), 256>>>(gamma, beta, out);
}